// round 9
// baseline (speedup 1.0000x reference)
#include <cuda_runtime.h>
#include <cuda_fp16.h>
#include <cstdint>

#define MM 32
#define KK 8192
#define NN 28672
#define N_TILE 128
#define K_TILE 128
#define NK_ITERS 64
#define A_STRIDE 272            // bytes per A smem row (128 halves + 8 pad)
#define W_STRIDE 144            // bytes per W smem row (128 int8 + 16 pad)
#define A_BYTES (MM * A_STRIDE)         // 8704
#define W_BYTES (K_TILE * W_STRIDE)     // 18432
#define STAGE_BYTES (A_BYTES + W_BYTES) // 27136
#define SMEM_BYTES (2 * STAGE_BYTES)    // 54272

__device__ __forceinline__ uint32_t prmt_(uint32_t a, uint32_t b, uint32_t s) {
    uint32_t d;
    asm("prmt.b32 %0,%1,%2,%3;" : "=r"(d) : "r"(a), "r"(b), "r"(s));
    return d;
}

// Two int8 values (low bytes of x0, x1) -> packed half2 {fp16(x0), fp16(x1)}.
// Exact: flip sign -> biased u=b+128; 0x64 exponent byte encodes 1024+u
// exactly in fp16; subtract 1152 -> b.
__device__ __forceinline__ uint32_t cvt_i8x2_h2(uint32_t x0, uint32_t x1) {
    uint32_t p = prmt_(x0, x1, 0x0040u) ^ 0x00008080u;  // [u0,u1,.,.]
    uint32_t h = prmt_(p, 0x64646464u, 0x4140u);        // [u0,64,u1,64]
    uint32_t magic = 0x64806480u;                       // half2(1152,1152)
    __half2 r = __hsub2(*reinterpret_cast<__half2*>(&h),
                        *reinterpret_cast<__half2*>(&magic));
    return *reinterpret_cast<uint32_t*>(&r);
}

__device__ __forceinline__ void mma16816(float* c, const uint32_t* a,
                                         uint32_t b0, uint32_t b1) {
    asm volatile(
        "mma.sync.aligned.m16n8k16.row.col.f32.f16.f16.f32 "
        "{%0,%1,%2,%3}, {%4,%5,%6,%7}, {%8,%9}, {%0,%1,%2,%3};"
        : "+f"(c[0]), "+f"(c[1]), "+f"(c[2]), "+f"(c[3])
        : "r"(a[0]), "r"(a[1]), "r"(a[2]), "r"(a[3]), "r"(b0), "r"(b1));
}

__device__ __forceinline__ void cp16(uint32_t dst_smem, const void* src) {
    asm volatile("cp.async.cg.shared.global [%0], [%1], 16;"
                 :: "r"(dst_smem), "l"(src));
}

// ---- shared compute core: one staged K_TILE chunk (fp16 A + int8 W in smem)
__device__ __forceinline__ void compute_stage(
    char* smem, uint32_t smem_u, int s, int warp, int lane, int g, int tg,
    float acc[2][2][4]) {
    const uint32_t sA = smem_u + s * STAGE_BYTES;
    const unsigned char* Wb =
        (const unsigned char*)(smem + s * STAGE_BYTES + A_BYTES);
    const int colb = warp * 16 + g;
    #pragma unroll
    for (int k16 = 0; k16 < 8; k16++) {
        const int kb = k16 * 16;
        uint32_t a[2][4];
        #pragma unroll
        for (int mf = 0; mf < 2; mf++) {
            uint32_t addr = sA + (mf * 16 + (lane & 15)) * A_STRIDE
                          + kb * 2 + (lane >> 4) * 16;
            asm volatile(
                "ldmatrix.sync.aligned.m8n8.x4.shared.b16 {%0,%1,%2,%3}, [%4];"
                : "=r"(a[mf][0]), "=r"(a[mf][1]),
                  "=r"(a[mf][2]), "=r"(a[mf][3])
                : "r"(addr));
        }
        const int rb = (kb + 2 * tg) * W_STRIDE;
        #pragma unroll
        for (int nf = 0; nf < 2; nf++) {
            const unsigned char* cp = Wb + colb + nf * 8 + rb;
            uint32_t x0 = cp[0];
            uint32_t x1 = cp[W_STRIDE];
            uint32_t x2 = cp[8 * W_STRIDE];
            uint32_t x3 = cp[9 * W_STRIDE];
            uint32_t b0 = cvt_i8x2_h2(x0, x1);
            uint32_t b1 = cvt_i8x2_h2(x2, x3);
            mma16816(acc[0][nf], a[0], b0, b1);
            mma16816(acc[1][nf], a[1], b0, b1);
        }
    }
}

// ============================================================================
// Kernel A (expected): act fp32, weight int32(widened int8), scale fp32,
// out fp32. Register-staged double buffer: LDGs for chunk kt+1 issue before
// computing chunk kt; STS after compute.
// ============================================================================
__global__ void __launch_bounds__(256, 2)
i8w_gemm_f32(const float* __restrict__ act,
             const int* __restrict__ w32,
             const float* __restrict__ scale,
             float* __restrict__ out) {
    extern __shared__ char smem[];
    const int tid  = threadIdx.x;
    const int warp = tid >> 5;
    const int lane = tid & 31;
    const int g  = lane >> 2;
    const int tg = lane & 3;
    const int n0 = blockIdx.x * N_TILE;
    const uint32_t smem_u = (uint32_t)__cvta_generic_to_shared(smem);

    float acc[2][2][4];
    #pragma unroll
    for (int mf = 0; mf < 2; mf++)
        #pragma unroll
        for (int nf = 0; nf < 2; nf++)
            #pragma unroll
            for (int r = 0; r < 4; r++) acc[mf][nf][r] = 0.f;

    float4   ra[4];     // A: 4 float4 per thread (16 halves after cvt)
    uint32_t rw[16];    // W: 64 int8 packed

    const int wrow = tid >> 1;
    const int wnh  = (tid & 1) * 64;

    auto fetch = [&](int kt) {
        const int k0 = kt * K_TILE;
        #pragma unroll
        for (int j = 0; j < 4; j++) {
            int c = tid + j * 256;
            int row = c >> 5, col4 = c & 31;
            ra[j] = __ldg((const float4*)(act + (size_t)row * KK + k0) + col4);
        }
        const int4* src = (const int4*)(w32 + (size_t)(k0 + wrow) * NN + n0 + wnh);
        #pragma unroll
        for (int i = 0; i < 16; i++) {
            int4 v = __ldg(src + i);
            rw[i] = prmt_(prmt_((uint32_t)v.x, (uint32_t)v.y, 0x0040u),
                          prmt_((uint32_t)v.z, (uint32_t)v.w, 0x0040u),
                          0x5410u);
        }
    };

    auto stage_sts = [&](int s) {
        char* base = smem + s * STAGE_BYTES;
        #pragma unroll
        for (int j = 0; j < 4; j++) {
            int c = tid + j * 256;
            int row = c >> 5, col4 = c & 31;
            __half2 lo = __floats2half2_rn(ra[j].x, ra[j].y);
            __half2 hi = __floats2half2_rn(ra[j].z, ra[j].w);
            uint2 u;
            u.x = *reinterpret_cast<uint32_t*>(&lo);
            u.y = *reinterpret_cast<uint32_t*>(&hi);
            *(uint2*)(base + row * A_STRIDE + col4 * 8) = u;
        }
        char* dst = base + A_BYTES + wrow * W_STRIDE + wnh;
        #pragma unroll
        for (int i = 0; i < 4; i++) {
            uint4 u = make_uint4(rw[4*i], rw[4*i+1], rw[4*i+2], rw[4*i+3]);
            *(uint4*)(dst + i * 16) = u;
        }
    };

    fetch(0);
    stage_sts(0);
    __syncthreads();
    for (int kt = 0; kt < NK_ITERS; kt++) {
        if (kt + 1 < NK_ITERS) fetch(kt + 1);   // overlap DRAM with HMMA below
        compute_stage(smem, smem_u, kt & 1, warp, lane, g, tg, acc);
        __syncthreads();
        if (kt + 1 < NK_ITERS) {
            stage_sts((kt + 1) & 1);
            __syncthreads();
        }
    }

    // epilogue: fp32 scale, round through fp16 (reference emits fp16), store fp32
    #pragma unroll
    for (int nf = 0; nf < 2; nf++) {
        const int col = n0 + warp * 16 + nf * 8 + 2 * tg;
        float2 s2 = *(const float2*)(scale + col);
        #pragma unroll
        for (int mf = 0; mf < 2; mf++) {
            int r0 = mf * 16 + g;
            float2 o0, o1;
            o0.x = __half2float(__float2half_rn(acc[mf][nf][0] * s2.x));
            o0.y = __half2float(__float2half_rn(acc[mf][nf][1] * s2.y));
            o1.x = __half2float(__float2half_rn(acc[mf][nf][2] * s2.x));
            o1.y = __half2float(__float2half_rn(acc[mf][nf][3] * s2.y));
            *(float2*)(out + (size_t)r0 * NN + col) = o0;
            *(float2*)(out + (size_t)(r0 + 8) * NN + col) = o1;
        }
    }
}

// ============================================================================
// Kernel B (fallback): act fp16, weight packed int8, scale fp16, out fp16.
// cp.async 2-stage pipeline.
// ============================================================================
__global__ void __launch_bounds__(256, 2)
i8w_gemm_f16(const __half* __restrict__ act,
             const int8_t* __restrict__ w8,
             const __half* __restrict__ scale,
             __half* __restrict__ out) {
    extern __shared__ char smem[];
    const int tid  = threadIdx.x;
    const int warp = tid >> 5;
    const int lane = tid & 31;
    const int g  = lane >> 2;
    const int tg = lane & 3;
    const int n0 = blockIdx.x * N_TILE;
    const uint32_t smem_u = (uint32_t)__cvta_generic_to_shared(smem);

    float acc[2][2][4];
    #pragma unroll
    for (int mf = 0; mf < 2; mf++)
        #pragma unroll
        for (int nf = 0; nf < 2; nf++)
            #pragma unroll
            for (int r = 0; r < 4; r++) acc[mf][nf][r] = 0.f;

    auto load_stage = [&](int s, int kt) {
        const int k0 = kt * K_TILE;
        const uint32_t sA = smem_u + s * STAGE_BYTES;
        const uint32_t sW = sA + A_BYTES;
        #pragma unroll
        for (int j = 0; j < 2; j++) {
            int c = tid + j * 256;
            int row = c >> 4, cc = c & 15;
            cp16(sA + row * A_STRIDE + cc * 16,
                 act + (size_t)row * KK + k0 + cc * 8);
        }
        #pragma unroll
        for (int j = 0; j < 4; j++) {
            int c = tid + j * 256;
            int row = c >> 3, cc = c & 7;
            cp16(sW + row * W_STRIDE + cc * 16,
                 w8 + (size_t)(k0 + row) * NN + n0 + cc * 16);
        }
        asm volatile("cp.async.commit_group;");
    };

    load_stage(0, 0);
    for (int kt = 0; kt < NK_ITERS; kt++) {
        if (kt + 1 < NK_ITERS) {
            load_stage((kt + 1) & 1, kt + 1);
            asm volatile("cp.async.wait_group 1;");
        } else {
            asm volatile("cp.async.wait_group 0;");
        }
        __syncthreads();
        compute_stage(smem, smem_u, kt & 1, warp, lane, g, tg, acc);
        __syncthreads();
    }

    #pragma unroll
    for (int nf = 0; nf < 2; nf++) {
        const int col = n0 + warp * 16 + nf * 8 + 2 * tg;
        float2 s2 = __half22float2(*(const __half2*)(scale + col));
        #pragma unroll
        for (int mf = 0; mf < 2; mf++) {
            int r0 = mf * 16 + g;
            *(__half2*)(out + (size_t)r0 * NN + col) =
                __floats2half2_rn(acc[mf][nf][0] * s2.x,
                                  acc[mf][nf][1] * s2.y);
            *(__half2*)(out + (size_t)(r0 + 8) * NN + col) =
                __floats2half2_rn(acc[mf][nf][2] * s2.x,
                                  acc[mf][nf][3] * s2.y);
        }
    }
}

extern "C" void kernel_launch(void* const* d_in, const int* in_sizes, int n_in,
                              void* d_out, int out_size) {
    const bool wide = (in_sizes[1] == KK * NN);  // widened int32 weights

    if (wide) {
        cudaFuncSetAttribute(i8w_gemm_f32,
                             cudaFuncAttributeMaxDynamicSharedMemorySize,
                             SMEM_BYTES);
        i8w_gemm_f32<<<NN / N_TILE, 256, SMEM_BYTES>>>(
            (const float*)d_in[0], (const int*)d_in[1],
            (const float*)d_in[2], (float*)d_out);
    } else {
        cudaFuncSetAttribute(i8w_gemm_f16,
                             cudaFuncAttributeMaxDynamicSharedMemorySize,
                             SMEM_BYTES);
        i8w_gemm_f16<<<NN / N_TILE, 256, SMEM_BYTES>>>(
            (const __half*)d_in[0], (const int8_t*)d_in[1],
            (const __half*)d_in[2], (__half*)d_out);
    }
}

// round 10
// speedup vs baseline: 1.7781x; 1.7781x over previous
#include <cuda_runtime.h>
#include <cuda_fp16.h>
#include <cstdint>

#define MM 32
#define KK 8192
#define NN 28672
#define N_TILE 128
#define K_TILE 64
#define NK_ITERS (KK / K_TILE)            // 128
#define A_STRIDE 144                      // 64 halves (128B) + 16 pad
#define WP_STRIDE 272                     // 128 u16 k-pairs (256B) + 16 pad
#define A_BYTES (MM * A_STRIDE)           // 4608
#define W_BYTES ((K_TILE / 2) * WP_STRIDE)// 8704
#define STAGE_BYTES (A_BYTES + W_BYTES)   // 13312
#define SMEM_BYTES (2 * STAGE_BYTES)      // 26624

__device__ __half g_act16[MM * KK];       // 512KB static scratch (allowed)

__device__ __forceinline__ uint32_t prmt_(uint32_t a, uint32_t b, uint32_t s) {
    uint32_t d;
    asm("prmt.b32 %0,%1,%2,%3;" : "=r"(d) : "r"(a), "r"(b), "r"(s));
    return d;
}

// u16 holding bytes [b0,b1] (int8) -> half2 {fp16(b0), fp16(b1)}. Exact:
// flip sign bit (biased u=b+128), splice 0x64 exponent (value 1024+u),
// subtract 1152.
__device__ __forceinline__ uint32_t cvt_pair_h2(uint32_t x) {
    uint32_t p = x ^ 0x00008080u;                 // [u0,u1,0,0]
    uint32_t h = prmt_(p, 0x64646464u, 0x4140u);  // [u0,64,u1,64]
    uint32_t magic = 0x64806480u;                 // half2(1152,1152)
    __half2 r = __hsub2(*reinterpret_cast<__half2*>(&h),
                        *reinterpret_cast<__half2*>(&magic));
    return *reinterpret_cast<uint32_t*>(&r);
}

__device__ __forceinline__ void mma16816(float* c, const uint32_t* a,
                                         uint32_t b0, uint32_t b1) {
    asm volatile(
        "mma.sync.aligned.m16n8k16.row.col.f32.f16.f16.f32 "
        "{%0,%1,%2,%3}, {%4,%5,%6,%7}, {%8,%9}, {%0,%1,%2,%3};"
        : "+f"(c[0]), "+f"(c[1]), "+f"(c[2]), "+f"(c[3])
        : "r"(a[0]), "r"(a[1]), "r"(a[2]), "r"(a[3]), "r"(b0), "r"(b1));
}

__device__ __forceinline__ void cp16(uint32_t dst_smem, const void* src) {
    asm volatile("cp.async.cg.shared.global [%0], [%1], 16;"
                 :: "r"(dst_smem), "l"(src));
}

// ---- pre-pass: act fp32 -> fp16 --------------------------------------------
__global__ void cvt_act_kernel(const float* __restrict__ act) {
    int i = blockIdx.x * blockDim.x + threadIdx.x;   // float2 index
    float2 v = ((const float2*)act)[i];
    ((__half2*)g_act16)[i] = __floats2half2_rn(v.x, v.y);
}

// ---- main GEMM -------------------------------------------------------------
__global__ void __launch_bounds__(256, 3)
i8w_gemm_f32(const int* __restrict__ w32,
             const float* __restrict__ scale,
             float* __restrict__ out) {
    extern __shared__ char smem[];
    const int tid  = threadIdx.x;
    const int warp = tid >> 5;
    const int lane = tid & 31;
    const int g  = lane >> 2;
    const int tg = lane & 3;
    const int n0 = blockIdx.x * N_TILE;
    const uint32_t smem_u = (uint32_t)__cvta_generic_to_shared(smem);

    // weight fetch assignment: thread owns k-pair row pr (k=2pr,2pr+1),
    // 16-n segment ns.
    const int pr = tid >> 3;     // 0..31
    const int ns = tid & 7;      // 0..7

    float acc[2][2][4];
    #pragma unroll
    for (int mf = 0; mf < 2; mf++)
        #pragma unroll
        for (int nf = 0; nf < 2; nf++)
            #pragma unroll
            for (int r = 0; r < 4; r++) acc[mf][nf][r] = 0.f;

    int4 ev[4], od[4];   // raw int32 weights, live across compute

    auto fetch = [&](int s, int kt) {
        const int k0 = kt * K_TILE;
        // A tile via cp.async (32 rows x 128B): one 16B chunk per thread
        {
            const int row = tid >> 3, c8 = tid & 7;
            cp16(smem_u + s * STAGE_BYTES + row * A_STRIDE + c8 * 16,
                 g_act16 + (size_t)row * KK + k0 + c8 * 8);
            asm volatile("cp.async.commit_group;");
        }
        const int4* se = (const int4*)(w32 + (size_t)(k0 + 2 * pr) * NN
                                       + n0 + ns * 16);
        const int4* so = (const int4*)(w32 + (size_t)(k0 + 2 * pr + 1) * NN
                                       + n0 + ns * 16);
        #pragma unroll
        for (int j = 0; j < 4; j++) ev[j] = __ldg(se + j);
        #pragma unroll
        for (int j = 0; j < 4; j++) od[j] = __ldg(so + j);
    };

    // pack int32->int8, interleave (k,k+1) pairs n-major, store 32B
    auto stage_w = [&](int s) {
        char* dst = smem + s * STAGE_BYTES + A_BYTES + pr * WP_STRIDE + ns * 32;
        uint32_t w[8];
        #pragma unroll
        for (int j = 0; j < 4; j++) {
            uint32_t pe = prmt_(prmt_((uint32_t)ev[j].x, (uint32_t)ev[j].y, 0x0040u),
                                prmt_((uint32_t)ev[j].z, (uint32_t)ev[j].w, 0x0040u),
                                0x5410u);
            uint32_t po = prmt_(prmt_((uint32_t)od[j].x, (uint32_t)od[j].y, 0x0040u),
                                prmt_((uint32_t)od[j].z, (uint32_t)od[j].w, 0x0040u),
                                0x5410u);
            w[2 * j]     = prmt_(pe, po, 0x5140u);  // [e0,o0,e1,o1]
            w[2 * j + 1] = prmt_(pe, po, 0x7362u);  // [e2,o2,e3,o3]
        }
        *(uint4*)dst        = make_uint4(w[0], w[1], w[2], w[3]);
        *(uint4*)(dst + 16) = make_uint4(w[4], w[5], w[6], w[7]);
    };

    const int colb = warp * 16 + g;
    auto compute = [&](int s) {
        const uint32_t sA = smem_u + s * STAGE_BYTES;
        const char* Wp = smem + s * STAGE_BYTES + A_BYTES;
        #pragma unroll
        for (int k16 = 0; k16 < 4; k16++) {
            const int kb = k16 * 16;
            uint32_t a[2][4];
            #pragma unroll
            for (int mf = 0; mf < 2; mf++) {
                uint32_t addr = sA + (mf * 16 + (lane & 15)) * A_STRIDE
                              + kb * 2 + (lane >> 4) * 16;
                asm volatile(
                    "ldmatrix.sync.aligned.m8n8.x4.shared.b16 {%0,%1,%2,%3}, [%4];"
                    : "=r"(a[mf][0]), "=r"(a[mf][1]),
                      "=r"(a[mf][2]), "=r"(a[mf][3])
                    : "r"(addr));
            }
            const int prb = k16 * 8 + tg;   // k-pair rows prb, prb+4
            #pragma unroll
            for (int nf = 0; nf < 2; nf++) {
                const int cb = (colb + nf * 8) * 2;
                uint32_t x0 = *(const unsigned short*)(Wp + prb * WP_STRIDE + cb);
                uint32_t x1 = *(const unsigned short*)(Wp + (prb + 4) * WP_STRIDE + cb);
                uint32_t b0 = cvt_pair_h2(x0);
                uint32_t b1 = cvt_pair_h2(x1);
                mma16816(acc[0][nf], a[0], b0, b1);
                mma16816(acc[1][nf], a[1], b0, b1);
            }
        }
    };

    // ---- pipeline: 1 barrier / iter, LDG latency hidden by compute --------
    fetch(0, 0);
    stage_w(0);
    asm volatile("cp.async.wait_group 0;");
    __syncthreads();
    for (int kt = 0; kt < NK_ITERS; kt++) {
        const int s = kt & 1;
        if (kt + 1 < NK_ITERS) fetch(s ^ 1, kt + 1);
        compute(s);
        if (kt + 1 < NK_ITERS) {
            stage_w(s ^ 1);
            asm volatile("cp.async.wait_group 0;");
        }
        __syncthreads();
    }

    // ---- epilogue: fp32 scale, round through fp16 (ref emits fp16), fp32 out
    #pragma unroll
    for (int nf = 0; nf < 2; nf++) {
        const int col = n0 + warp * 16 + nf * 8 + 2 * tg;
        float2 s2 = *(const float2*)(scale + col);
        #pragma unroll
        for (int mf = 0; mf < 2; mf++) {
            int r0 = mf * 16 + g;
            float2 o0, o1;
            o0.x = __half2float(__float2half_rn(acc[mf][nf][0] * s2.x));
            o0.y = __half2float(__float2half_rn(acc[mf][nf][1] * s2.y));
            o1.x = __half2float(__float2half_rn(acc[mf][nf][2] * s2.x));
            o1.y = __half2float(__float2half_rn(acc[mf][nf][3] * s2.y));
            *(float2*)(out + (size_t)r0 * NN + col) = o0;
            *(float2*)(out + (size_t)(r0 + 8) * NN + col) = o1;
        }
    }
}

extern "C" void kernel_launch(void* const* d_in, const int* in_sizes, int n_in,
                              void* d_out, int out_size) {
    const float* act   = (const float*)d_in[0];
    const int*   w32   = (const int*)d_in[1];
    const float* scale = (const float*)d_in[2];
    float*       out   = (float*)d_out;

    cvt_act_kernel<<<(MM * KK / 2) / 256, 256>>>(act);

    cudaFuncSetAttribute(i8w_gemm_f32,
                         cudaFuncAttributeMaxDynamicSharedMemorySize,
                         SMEM_BYTES);
    i8w_gemm_f32<<<NN / N_TILE, 256, SMEM_BYTES>>>(w32, scale, out);
}